// round 2
// baseline (speedup 1.0000x reference)
#include <cuda_runtime.h>

// ---------------- problem constants ----------------
#define NLINES 2048
#define NEP    4096          // endpoints = 2*NLINES
#define NK     2048          // keypoints
#define NC     256           // descriptor channels
#define NTOT   6144          // NEP + NK
#define HC     128
#define WC     128
#define EDGE_CAP 65536

// output offsets (float32, concatenated in reference return order)
#define OFF_POINTS   0          // (1, 6144, 2)   -> 12288
#define OFF_SCORES   12288      // (1, 6144)      -> 6144
#define OFF_DESCS    18432      // (1, 256, 6144) -> 1572864
#define OFF_NEWLINES 1591296    // (1, 2048, 2,2) -> 8192
#define OFF_JIDX     1599488    // (1, 2048, 2)   -> 4096
#define OFF_LS       1603584    // (1, 2048)      -> 2048

// ---------------- scratch (no allocations allowed) ----------------
__device__ int g_suppress[NK];
__device__ int g_root[NEP];
__device__ int g_clusters[NEP];
__device__ int g_edge_cnt;
__device__ int g_edges[EDGE_CAP];
__device__ unsigned long long g_accx[NEP];
__device__ unsigned long long g_accy[NEP];
__device__ unsigned long long g_accs[NEP];
__device__ int g_cnt[NEP];

// ---------------- kernels ----------------

// zero scratch
__global__ void k_init() {
    int i = blockIdx.x * blockDim.x + threadIdx.x;
    if (i < NEP) {
        g_accx[i] = 0ull; g_accy[i] = 0ull; g_accs[i] = 0ull; g_cnt[i] = 0;
    }
    if (i < NK) g_suppress[i] = 0;
    if (i == 0) g_edge_cnt = 0;
}

// normalized line scores: ls = s / (1e-8 + max(s))
__global__ void k_ls(const float* __restrict__ ls_in, float* __restrict__ out) {
    __shared__ float red[1024];
    int t = threadIdx.x;
    float v = fmaxf(ls_in[t], ls_in[t + 1024]);
    red[t] = v;
    __syncthreads();
    for (int s = 512; s > 0; s >>= 1) {
        if (t < s) red[t] = fmaxf(red[t], red[t + s]);
        __syncthreads();
    }
    float denom = 1e-8f + red[0];
    out[OFF_LS + t]        = ls_in[t] / denom;
    out[OFF_LS + t + 1024] = ls_in[t + 1024] / denom;
}

// keypoint suppression: any endpoint within dist < 4  -> suppress
// grid 32 blocks x 256 thr: block = (ep quarter q, kp group g)
__global__ void k_keep(const float* __restrict__ ep, const float* __restrict__ kp) {
    __shared__ float2 se[1024];
    int t = threadIdx.x;
    int q = blockIdx.x >> 3;   // endpoint quarter 0..3
    int g = blockIdx.x & 7;    // keypoint group 0..7
    const float2* ep2 = (const float2*)ep;
    for (int i = t; i < 1024; i += 256) se[i] = ep2[q * 1024 + i];
    __syncthreads();
    int kidx = g * 256 + t;
    float kx = kp[2 * kidx], ky = kp[2 * kidx + 1];
    int flag = 0;
    #pragma unroll 4
    for (int j = 0; j < 1024; ++j) {
        float dx = kx - se[j].x;
        float dy = ky - se[j].y;
        if (dx * dx + dy * dy < 16.0f) flag = 1;
    }
    if (flag) atomicOr(&g_suppress[kidx], 1);
}

// write kp half of points/scores
__global__ void k_kpwrite(const float* __restrict__ kp, const float* __restrict__ ksc,
                          float* __restrict__ out) {
    int k = blockIdx.x * blockDim.x + threadIdx.x;
    if (k >= NK) return;
    int sup = g_suppress[k];
    out[OFF_POINTS + 2 * (NEP + k)]     = sup ? 0.f : kp[2 * k];
    out[OFF_POINTS + 2 * (NEP + k) + 1] = sup ? 0.f : kp[2 * k + 1];
    out[OFF_SCORES + NEP + k]           = sup ? 0.f : ksc[k];
}

// copy (masked) keypoint descriptors into all_descs columns [4096,6144)
__global__ void k_kd(const float* __restrict__ desc, float* __restrict__ out) {
    int gid = blockIdx.x * blockDim.x + threadIdx.x;   // 524288
    int c = gid >> 11;           // /2048
    int k = gid & 2047;
    float v = g_suppress[k] ? 0.f : desc[c * NK + k];
    out[OFF_DESCS + c * NTOT + NEP + k] = v;
}

// build sparse edge list: pairs with d^2 <= 9 (eps=3), i<j
__global__ void k_edges(const float* __restrict__ ep) {
    __shared__ float2 sp[NEP];
    int t = threadIdx.x;
    const float2* ep2 = (const float2*)ep;
    for (int i = t; i < NEP; i += 256) sp[i] = ep2[i];
    __syncthreads();
    int gid = blockIdx.x * 256 + t;     // 65536 work items
    int i  = gid >> 4;
    int ch = gid & 15;
    float2 pi = sp[i];
    int j0 = ch * 256;
    #pragma unroll 4
    for (int j = j0; j < j0 + 256; ++j) {
        if (j <= i) continue;
        float dx = pi.x - sp[j].x;
        float dy = pi.y - sp[j].y;
        if (dx * dx + dy * dy <= 9.0f) {
            int idx = atomicAdd(&g_edge_cnt, 1);
            if (idx < EDGE_CAP) g_edges[idx] = (i << 16) | j;
        }
    }
}

// connected components + dense rank, single block 1024 threads
__global__ void __launch_bounds__(1024) k_cc() {
    __shared__ int lab[NEP];
    __shared__ int rnk[NEP];
    __shared__ int sc[1024];
    __shared__ int s_changed;
    int t = threadIdx.x;
    for (int i = t; i < NEP; i += 1024) lab[i] = i;
    __syncthreads();
    int E = g_edge_cnt; if (E > EDGE_CAP) E = EDGE_CAP;

    for (int it = 0; it < 64; ++it) {
        if (t == 0) s_changed = 0;
        __syncthreads();
        for (int e = t; e < E; e += 1024) {
            int pr = g_edges[e];
            int i = pr >> 16, j = pr & 0xffff;
            int a = lab[i], b = lab[j];
            if (a < b)      { int old = atomicMin(&lab[j], a); if (old > a) s_changed = 1; }
            else if (b < a) { int old = atomicMin(&lab[i], b); if (old > b) s_changed = 1; }
        }
        __syncthreads();
        for (int i = t; i < NEP; i += 1024) {
            int l = lab[i];
            int l2 = lab[l];
            if (l2 < l) { lab[i] = l2; s_changed = 1; }
        }
        __syncthreads();
        int ch = s_changed;
        __syncthreads();
        if (!ch) break;
    }

    // dense rank of roots (exclusive scan of present flags)
    int base = t * 4;
    int p[4], pre[4], lsum = 0;
    #pragma unroll
    for (int k = 0; k < 4; ++k) {
        p[k] = (lab[base + k] == base + k) ? 1 : 0;
        pre[k] = lsum;
        lsum += p[k];
    }
    sc[t] = lsum;
    __syncthreads();
    for (int off = 1; off < 1024; off <<= 1) {
        int add = 0;
        if (t >= off) add = sc[t - off];
        __syncthreads();
        sc[t] += add;
        __syncthreads();
    }
    int excl = sc[t] - lsum;
    #pragma unroll
    for (int k = 0; k < 4; ++k) rnk[base + k] = excl + pre[k];
    __syncthreads();
    for (int i = t; i < NEP; i += 1024) {
        int r = lab[i];
        g_root[i] = r;
        g_clusters[i] = rnk[r];
    }
}

// deterministic segment sums (fixed-point int64 atomics)
__global__ void k_segsum(const float* __restrict__ ep, const float* __restrict__ out_ls) {
    int i = blockIdx.x * blockDim.x + threadIdx.x;
    if (i >= NEP) return;
    int c = g_clusters[i];
    float x = ep[2 * i], y = ep[2 * i + 1];
    float s = out_ls[i >> 1];   // ep_scores = repeat(ls, 2)
    atomicAdd(&g_accx[c], (unsigned long long)__float2ll_rn(x * 8388608.f));     // 2^23
    atomicAdd(&g_accy[c], (unsigned long long)__float2ll_rn(y * 8388608.f));
    atomicAdd(&g_accs[c], (unsigned long long)__float2ll_rn(s * 1073741824.f));  // 2^30
    atomicAdd(&g_cnt[c], 1);
}

// finish means; write junction points/scores (all 4096 slots; empty -> 0)
__global__ void k_avg(float* __restrict__ out) {
    int s = blockIdx.x * blockDim.x + threadIdx.x;
    if (s >= NEP) return;
    int c = g_cnt[s];
    float jx = 0.f, jy = 0.f, js = 0.f;
    if (c > 0) {
        float fc = (float)c;
        jx = (float)((double)g_accx[s] * (1.0 / 8388608.0)) / fc;
        jy = (float)((double)g_accy[s] * (1.0 / 8388608.0)) / fc;
        js = (float)((double)g_accs[s] * (1.0 / 1073741824.0)) / fc;
    }
    out[OFF_POINTS + 2 * s]     = jx;
    out[OFF_POINTS + 2 * s + 1] = jy;
    out[OFF_SCORES + s]         = js;
}

// new_lines = junctions[clusters], lines_junc_idx = clusters (as float)
__global__ void k_newlines(float* __restrict__ out) {
    int e = blockIdx.x * blockDim.x + threadIdx.x;
    if (e >= NEP) return;
    int c = g_clusters[e];
    out[OFF_NEWLINES + 2 * e]     = out[OFF_POINTS + 2 * c];
    out[OFF_NEWLINES + 2 * e + 1] = out[OFF_POINTS + 2 * c + 1];
    out[OFF_JIDX + e]             = (float)c;
}

// SuperPoint-style bilinear descriptor sampling + L2 normalize
// one block per junction, thread per channel
__global__ void __launch_bounds__(256) k_sample(const float* __restrict__ allD,
                                                float* __restrict__ out) {
    int p = blockIdx.x;          // 0..4095
    int c = threadIdx.x;         // 0..255
    float px = out[OFF_POINTS + 2 * p];
    float py = out[OFF_POINTS + 2 * p + 1];

    float gx = ((px - 3.5f) / 1019.5f) * 2.0f - 1.0f;
    float gy = ((py - 3.5f) / 1019.5f) * 2.0f - 1.0f;
    float fx = (gx + 1.0f) * 0.5f * 127.0f;
    float fy = (gy + 1.0f) * 0.5f * 127.0f;
    float x0 = fminf(fmaxf(floorf(fx), 0.f), 127.f);
    float y0 = fminf(fmaxf(floorf(fy), 0.f), 127.f);
    float x1 = fminf(fmaxf(x0 + 1.0f, 0.f), 127.f);
    float y1 = fminf(fmaxf(y0 + 1.0f, 0.f), 127.f);
    float wx = fx - x0;
    float wy = fy - y0;
    int xi0 = (int)x0, xi1 = (int)x1, yi0 = (int)y0, yi1 = (int)y1;

    const float* pl = allD + c * (HC * WC);
    float v = pl[yi0 * WC + xi0] * (1.f - wx) * (1.f - wy)
            + pl[yi0 * WC + xi1] * wx * (1.f - wy)
            + pl[yi1 * WC + xi0] * (1.f - wx) * wy
            + pl[yi1 * WC + xi1] * wx * wy;

    __shared__ float red[256];
    red[c] = v * v;
    __syncthreads();
    for (int s = 128; s > 0; s >>= 1) {
        if (c < s) red[c] += red[c + s];
        __syncthreads();
    }
    if (c == 0) red[0] = 1.0f / fmaxf(sqrtf(red[0]), 1e-12f);
    __syncthreads();
    out[OFF_DESCS + c * NTOT + p] = v * red[0];
}

// ---------------- launch ----------------
extern "C" void kernel_launch(void* const* d_in, const int* in_sizes, int n_in,
                              void* d_out, int out_size) {
    const float* lines     = (const float*)d_in[0];   // (1,2048,2,2) == endpoints (4096,2)
    const float* line_sc   = (const float*)d_in[1];   // (1,2048)
    const float* keypoints = (const float*)d_in[2];   // (1,2048,2)
    const float* kp_sc     = (const float*)d_in[3];   // (1,2048)
    const float* desc      = (const float*)d_in[4];   // (1,256,2048)
    const float* allD      = (const float*)d_in[5];   // (1,256,128,128)
    float* out = (float*)d_out;

    k_init<<<16, 256>>>();
    k_ls<<<1, 1024>>>(line_sc, out);
    k_keep<<<32, 256>>>(lines, keypoints);
    k_kpwrite<<<8, 256>>>(keypoints, kp_sc, out);
    k_kd<<<2048, 256>>>(desc, out);
    k_edges<<<256, 256>>>(lines);
    k_cc<<<1, 1024>>>();
    k_segsum<<<16, 256>>>(lines, out + OFF_LS);
    k_avg<<<16, 256>>>(out);
    k_newlines<<<16, 256>>>(out);
    k_sample<<<NEP, 256>>>(allD, out);
}

// round 4
// speedup vs baseline: 1.4323x; 1.4323x over previous
#include <cuda_runtime.h>

// ---------------- problem constants ----------------
#define NLINES 2048
#define NEP    4096          // endpoints = 2*NLINES
#define NK     2048          // keypoints
#define NC     256           // descriptor channels
#define NTOT   6144          // NEP + NK
#define HC     128
#define WC     128
#define EB_CAP 256           // per-block edge cap (expected ~4/block)
#define SE_CAP 8192          // shared edge-list cap in k_mid (expected ~230 total)

// output offsets (float32, concatenated in reference return order)
#define OFF_POINTS   0          // (1, 6144, 2)   -> 12288
#define OFF_SCORES   12288      // (1, 6144)      -> 6144
#define OFF_DESCS    18432      // (1, 256, 6144) -> 1572864
#define OFF_NEWLINES 1591296    // (1, 2048, 2,2) -> 8192
#define OFF_JIDX     1599488    // (1, 2048, 2)   -> 4096
#define OFF_LS       1603584    // (1, 2048)      -> 2048

// fixed-point scales (commutative integer sums -> deterministic)
#define FX_COORD 65536.0f        // 2^16 ; sum <= 31*1024*2^16 < 2^31
#define FX_SCORE 33554432.0f     // 2^25 ; sum <= 63*2^25 < 2^31

// ---------------- scratch ----------------
__device__ int g_suppress[NK];
__device__ int g_edges[64 * EB_CAP];
__device__ int g_bcnt[64];

// =====================================================================
// k_front: role-switched blocks
//   blocks [0,64)   : keypoint suppression, 8 warps x 4 kp per warp
//   blocks [64,128) : edge-list build, 4 endpoints per thread
//   block  128      : line-score normalization
// =====================================================================
__global__ void __launch_bounds__(256) k_front(const float* __restrict__ lines,
                                               const float* __restrict__ line_sc,
                                               const float* __restrict__ kp,
                                               float* __restrict__ out) {
    __shared__ float2 se[NEP];
    __shared__ int s_cnt;
    __shared__ float red[256];
    int t = threadIdx.x;
    int role = blockIdx.x;

    if (role < 128) {
        const float2* ep2 = (const float2*)lines;
        for (int i = t; i < NEP; i += 256) se[i] = ep2[i];
    }
    if (role >= 64 && role < 128 && t == 0) s_cnt = 0;
    __syncthreads();

    if (role < 64) {
        // ---- keypoint suppression ----
        int w = t >> 5, lane = t & 31;
        int kb = (role * 8 + w) * 4;             // 4 keypoints per warp
        float kx0 = kp[2*kb],   ky0 = kp[2*kb+1];
        float kx1 = kp[2*kb+2], ky1 = kp[2*kb+3];
        float kx2 = kp[2*kb+4], ky2 = kp[2*kb+5];
        float kx3 = kp[2*kb+6], ky3 = kp[2*kb+7];
        bool f0=false, f1=false, f2=false, f3=false;
        for (int j = lane; j < NEP; j += 32) {
            float2 e = se[j];
            float dx, dy;
            dx = kx0-e.x; dy = ky0-e.y; f0 |= (dx*dx+dy*dy < 16.0f);
            dx = kx1-e.x; dy = ky1-e.y; f1 |= (dx*dx+dy*dy < 16.0f);
            dx = kx2-e.x; dy = ky2-e.y; f2 |= (dx*dx+dy*dy < 16.0f);
            dx = kx3-e.x; dy = ky3-e.y; f3 |= (dx*dx+dy*dy < 16.0f);
        }
        int a0 = __any_sync(0xffffffffu, f0);
        int a1 = __any_sync(0xffffffffu, f1);
        int a2 = __any_sync(0xffffffffu, f2);
        int a3 = __any_sync(0xffffffffu, f3);
        if (lane == 0) {
            g_suppress[kb]   = a0;
            g_suppress[kb+1] = a1;
            g_suppress[kb+2] = a2;
            g_suppress[kb+3] = a3;
        }
    } else if (role < 128) {
        // ---- edge build: block owns i in [64b, 64b+64) ----
        int b = role - 64;
        int ib = b * 64 + (t >> 4) * 4;          // 4 i's per thread
        int jc = (t & 15) * 256;                 // j chunk
        float2 p0 = se[ib], p1 = se[ib+1], p2 = se[ib+2], p3 = se[ib+3];
        for (int j = jc; j < jc + 256; ++j) {
            float2 e = se[j];
            float dx, dy;
            dx = p0.x-e.x; dy = p0.y-e.y;
            if (j > ib   && dx*dx+dy*dy <= 9.0f) { int x = atomicAdd(&s_cnt,1); if (x < EB_CAP) g_edges[b*EB_CAP+x] = (ib    <<16)|j; }
            dx = p1.x-e.x; dy = p1.y-e.y;
            if (j > ib+1 && dx*dx+dy*dy <= 9.0f) { int x = atomicAdd(&s_cnt,1); if (x < EB_CAP) g_edges[b*EB_CAP+x] = ((ib+1)<<16)|j; }
            dx = p2.x-e.x; dy = p2.y-e.y;
            if (j > ib+2 && dx*dx+dy*dy <= 9.0f) { int x = atomicAdd(&s_cnt,1); if (x < EB_CAP) g_edges[b*EB_CAP+x] = ((ib+2)<<16)|j; }
            dx = p3.x-e.x; dy = p3.y-e.y;
            if (j > ib+3 && dx*dx+dy*dy <= 9.0f) { int x = atomicAdd(&s_cnt,1); if (x < EB_CAP) g_edges[b*EB_CAP+x] = ((ib+3)<<16)|j; }
        }
        __syncthreads();
        if (t == 0) g_bcnt[b] = s_cnt < EB_CAP ? s_cnt : EB_CAP;
    } else {
        // ---- line-score normalization ----
        float v = -1e30f;
        for (int k = t; k < NLINES; k += 256) v = fmaxf(v, line_sc[k]);
        red[t] = v;
        __syncthreads();
        for (int s = 128; s > 0; s >>= 1) {
            if (t < s) red[t] = fmaxf(red[t], red[t + s]);
            __syncthreads();
        }
        float denom = 1e-8f + red[0];
        for (int k = t; k < NLINES; k += 256) out[OFF_LS + k] = line_sc[k] / denom;
    }
}

// =====================================================================
// k_mid: single block, 1024 threads, all-dynamic shared
//   CC -> dense rank -> fixed-point segment means -> junctions,
//   scores, new_lines, lines_junc_idx
// =====================================================================
__global__ void __launch_bounds__(1024) k_mid(const float* __restrict__ lines,
                                              float* __restrict__ out) {
    extern __shared__ int sm[];
    int* lab  = sm;               // 4096
    int* rnk  = lab  + 4096;      // 4096
    int* imap = rnk  + 4096;      // 4096 (dense slot -> root, or -1)
    int* ax   = imap + 4096;      // 4096
    int* ay   = ax   + 4096;      // 4096
    int* as   = ay   + 4096;      // 4096
    int* cn   = as   + 4096;      // 4096
    int* sE   = cn   + 4096;      // SE_CAP
    int* scn  = sE   + SE_CAP;    // 1024
    int* soff = scn  + 1024;      // 65
    int* flg  = soff + 66;        // 1

    int t = threadIdx.x;

    // gather per-block edge segments
    if (t == 0) {
        int acc = 0;
        for (int b = 0; b < 64; ++b) { soff[b] = acc; acc += g_bcnt[b]; }
        soff[64] = acc;
    }
    for (int i = t; i < NEP; i += 1024) lab[i] = i;
    __syncthreads();
    int E = soff[64]; if (E > SE_CAP) E = SE_CAP;
    for (int s = t; s < 64 * EB_CAP; s += 1024) {
        int b = s / EB_CAP, e = s % EB_CAP;
        if (e < g_bcnt[b]) { int d = soff[b] + e; if (d < SE_CAP) sE[d] = g_edges[s]; }
    }
    __syncthreads();

    // connected components (min-label fixpoint; schedule-independent result)
    for (int it = 0; it < 64; ++it) {
        if (t == 0) flg[0] = 0;
        __syncthreads();
        for (int e = t; e < E; e += 1024) {
            int pr = sE[e];
            int i = pr >> 16, j = pr & 0xffff;
            int a = lab[i], b = lab[j];
            if (a < b)      { int old = atomicMin(&lab[j], a); if (old > a) flg[0] = 1; }
            else if (b < a) { int old = atomicMin(&lab[i], b); if (old > b) flg[0] = 1; }
        }
        __syncthreads();
        for (int i = t; i < NEP; i += 1024) {
            int l = lab[i], l2 = lab[l];
            if (l2 < l) { lab[i] = l2; flg[0] = 1; }
        }
        __syncthreads();
        int ch = flg[0];
        __syncthreads();
        if (!ch) break;
    }

    // dense rank of roots (exclusive scan over presence flags, 4/thread)
    int base = t * 4;
    int pr4[4], pre[4], lsum = 0;
    #pragma unroll
    for (int k = 0; k < 4; ++k) {
        pr4[k] = (lab[base + k] == base + k) ? 1 : 0;
        pre[k] = lsum;
        lsum += pr4[k];
    }
    scn[t] = lsum;
    __syncthreads();
    for (int off = 1; off < 1024; off <<= 1) {
        int add = 0;
        if (t >= off) add = scn[t - off];
        __syncthreads();
        scn[t] += add;
        __syncthreads();
    }
    int excl = scn[t] - lsum;
    #pragma unroll
    for (int k = 0; k < 4; ++k) rnk[base + k] = excl + pre[k];
    __syncthreads();

    // zero accumulators + inverse map
    for (int s = t; s < NEP; s += 1024) {
        ax[s] = 0; ay[s] = 0; as[s] = 0; cn[s] = 0; imap[s] = -1;
    }
    __syncthreads();
    for (int i = t; i < NEP; i += 1024)
        if (lab[i] == i) imap[rnk[i]] = i;
    __syncthreads();

    // fixed-point segment sums (shared atomics; commutative -> deterministic)
    const float2* ep2 = (const float2*)lines;
    for (int i = t; i < NEP; i += 1024) {
        float2 e = ep2[i];
        float sc = out[OFF_LS + (i >> 1)];      // ep_scores = repeat(ls, 2)
        int r = lab[i];
        atomicAdd(&ax[r], __float2int_rn(e.x * FX_COORD));
        atomicAdd(&ay[r], __float2int_rn(e.y * FX_COORD));
        atomicAdd(&as[r], __float2int_rn(sc * FX_SCORE));
        atomicAdd(&cn[r], 1);
    }
    __syncthreads();

    // junction points + scores (all 4096 slots; empty -> 0)
    for (int s = t; s < NEP; s += 1024) {
        int r = imap[s];
        float jx = 0.f, jy = 0.f, js = 0.f;
        if (r >= 0) {
            float ic = 1.0f / (float)cn[r];
            jx = (float)ax[r] * (1.0f / FX_COORD) * ic;
            jy = (float)ay[r] * (1.0f / FX_COORD) * ic;
            js = (float)as[r] * (1.0f / FX_SCORE) * ic;
        }
        out[OFF_POINTS + 2*s]     = jx;
        out[OFF_POINTS + 2*s + 1] = jy;
        out[OFF_SCORES + s]       = js;
    }

    // new_lines + lines_junc_idx (recompute means from shared; bitwise equal)
    for (int e = t; e < NEP; e += 1024) {
        int r = lab[e];
        int c = rnk[r];
        float ic = 1.0f / (float)cn[r];
        out[OFF_NEWLINES + 2*e]     = (float)ax[r] * (1.0f / FX_COORD) * ic;
        out[OFF_NEWLINES + 2*e + 1] = (float)ay[r] * (1.0f / FX_COORD) * ic;
        out[OFF_JIDX + e]           = (float)c;
    }
}

// =====================================================================
// k_back: blocks [0,512): float4 keypoint-descriptor copy (masked)
//         block 512     : keypoint points/scores
// =====================================================================
__global__ void __launch_bounds__(256) k_back(const float* __restrict__ desc,
                                              const float* __restrict__ kp,
                                              const float* __restrict__ ksc,
                                              float* __restrict__ out) {
    int t = threadIdx.x;
    if (blockIdx.x < 512) {
        int idx = blockIdx.x * 256 + t;          // 131072 float4s
        int c  = idx >> 9;                       // /512
        int kq = idx & 511;                      // float4 within row
        const float4* d4 = (const float4*)desc;
        float4 v = d4[c * 512 + kq];
        int k4 = kq * 4;
        if (g_suppress[k4])     v.x = 0.f;
        if (g_suppress[k4 + 1]) v.y = 0.f;
        if (g_suppress[k4 + 2]) v.z = 0.f;
        if (g_suppress[k4 + 3]) v.w = 0.f;
        float4* o4 = (float4*)(out + OFF_DESCS + c * NTOT + NEP);
        o4[kq] = v;
    } else {
        for (int k = t; k < NK; k += 256) {
            int sup = g_suppress[k];
            out[OFF_POINTS + 2*(NEP + k)]     = sup ? 0.f : kp[2*k];
            out[OFF_POINTS + 2*(NEP + k) + 1] = sup ? 0.f : kp[2*k + 1];
            out[OFF_SCORES + NEP + k]         = sup ? 0.f : ksc[k];
        }
    }
}

// =====================================================================
// k_sample: 128 blocks x 256 thr. Block = 32 consecutive points.
//   warp w handles channels [32w, 32w+32), lane = point. v[32] in regs,
//   cross-warp smem reduce for the L2 norm, fully coalesced stores.
// =====================================================================
__global__ void __launch_bounds__(256) k_sample(const float* __restrict__ allD,
                                                float* __restrict__ out) {
    int w = threadIdx.x >> 5, lane = threadIdx.x & 31;
    int p = blockIdx.x * 32 + lane;

    float px = out[OFF_POINTS + 2*p];
    float py = out[OFF_POINTS + 2*p + 1];

    float gx = ((px - 3.5f) / 1019.5f) * 2.0f - 1.0f;
    float gy = ((py - 3.5f) / 1019.5f) * 2.0f - 1.0f;
    float fx = (gx + 1.0f) * 0.5f * 127.0f;
    float fy = (gy + 1.0f) * 0.5f * 127.0f;
    float x0 = fminf(fmaxf(floorf(fx), 0.f), 127.f);
    float y0 = fminf(fmaxf(floorf(fy), 0.f), 127.f);
    float x1 = fminf(fmaxf(x0 + 1.0f, 0.f), 127.f);
    float y1 = fminf(fmaxf(y0 + 1.0f, 0.f), 127.f);
    float wx = fx - x0;
    float wy = fy - y0;
    int a00 = (int)y0 * WC + (int)x0;
    int a01 = (int)y0 * WC + (int)x1;
    int a10 = (int)y1 * WC + (int)x0;
    int a11 = (int)y1 * WC + (int)x1;
    float w00 = (1.f - wx) * (1.f - wy);
    float w01 = wx * (1.f - wy);
    float w10 = (1.f - wx) * wy;
    float w11 = wx * wy;

    const float* bpl = allD + (size_t)w * 32 * (HC * WC);
    float v[32];
    float ssq = 0.f;
    #pragma unroll
    for (int ci = 0; ci < 32; ++ci) {
        const float* pl = bpl + ci * (HC * WC);
        float vv = pl[a00] * w00 + pl[a01] * w01 + pl[a10] * w10 + pl[a11] * w11;
        v[ci] = vv;
        ssq += vv * vv;
    }

    __shared__ float sred[8][32];
    sred[w][lane] = ssq;
    __syncthreads();
    float tot = sred[0][lane] + sred[1][lane] + sred[2][lane] + sred[3][lane]
              + sred[4][lane] + sred[5][lane] + sred[6][lane] + sred[7][lane];
    float inv = 1.0f / fmaxf(sqrtf(tot), 1e-12f);

    float* ob = out + OFF_DESCS + (size_t)w * 32 * NTOT + p;
    #pragma unroll
    for (int ci = 0; ci < 32; ++ci)
        ob[ci * NTOT] = v[ci] * inv;
}

// ---------------- launch ----------------
extern "C" void kernel_launch(void* const* d_in, const int* in_sizes, int n_in,
                              void* d_out, int out_size) {
    const float* lines     = (const float*)d_in[0];   // (1,2048,2,2)
    const float* line_sc   = (const float*)d_in[1];   // (1,2048)
    const float* keypoints = (const float*)d_in[2];   // (1,2048,2)
    const float* kp_sc     = (const float*)d_in[3];   // (1,2048)
    const float* desc      = (const float*)d_in[4];   // (1,256,2048)
    const float* allD      = (const float*)d_in[5];   // (1,256,128,128)
    float* out = (float*)d_out;

    static const int MID_SMEM = (4096 * 7 + SE_CAP + 1024 + 80) * 4;
    cudaFuncSetAttribute(k_mid, cudaFuncAttributeMaxDynamicSharedMemorySize, MID_SMEM);

    k_front<<<129, 256>>>(lines, line_sc, keypoints, out);
    k_mid<<<1, 1024, MID_SMEM>>>(lines, out);
    k_back<<<513, 256>>>(desc, keypoints, kp_sc, out);
    k_sample<<<128, 256>>>(allD, out);
}

// round 5
// speedup vs baseline: 1.6475x; 1.1503x over previous
#include <cuda_runtime.h>

// ---------------- problem constants ----------------
#define NLINES 2048
#define NEP    4096          // endpoints = 2*NLINES
#define NK     2048          // keypoints
#define NC     256           // descriptor channels
#define NTOT   6144          // NEP + NK
#define HC     128
#define WC     128
#define EB_CAP 256           // per-block edge cap (expected ~4/block)
#define SE_CAP 8192          // shared edge-list cap in k_mid (expected ~230 total)

// output offsets (float32, concatenated in reference return order)
#define OFF_POINTS   0          // (1, 6144, 2)   -> 12288
#define OFF_SCORES   12288      // (1, 6144)      -> 6144
#define OFF_DESCS    18432      // (1, 256, 6144) -> 1572864
#define OFF_NEWLINES 1591296    // (1, 2048, 2,2) -> 8192
#define OFF_JIDX     1599488    // (1, 2048, 2)   -> 4096
#define OFF_LS       1603584    // (1, 2048)      -> 2048

// fixed-point scales (commutative integer sums -> deterministic)
#define FX_COORD 65536.0f        // 2^16
#define FX_SCORE 33554432.0f     // 2^25

// ---------------- scratch ----------------
__device__ int g_suppress[NK];
__device__ int g_edges[64 * EB_CAP];
__device__ int g_bcnt[64];

// =====================================================================
// k_front: role-switched blocks
//   blocks [0,64)   : keypoint suppression, 8 warps x 4 kp per warp
//   blocks [64,128) : edge-list build, 4 endpoints per thread
//   block  128      : line-score normalization
// =====================================================================
__global__ void __launch_bounds__(256) k_front(const float* __restrict__ lines,
                                               const float* __restrict__ line_sc,
                                               const float* __restrict__ kp,
                                               float* __restrict__ out) {
    __shared__ float2 se[NEP];
    __shared__ int s_cnt;
    __shared__ float red[256];
    int t = threadIdx.x;
    int role = blockIdx.x;

    if (role < 128) {
        const float2* ep2 = (const float2*)lines;
        for (int i = t; i < NEP; i += 256) se[i] = ep2[i];
    }
    if (role >= 64 && role < 128 && t == 0) s_cnt = 0;
    __syncthreads();

    if (role < 64) {
        int w = t >> 5, lane = t & 31;
        int kb = (role * 8 + w) * 4;
        float kx0 = kp[2*kb],   ky0 = kp[2*kb+1];
        float kx1 = kp[2*kb+2], ky1 = kp[2*kb+3];
        float kx2 = kp[2*kb+4], ky2 = kp[2*kb+5];
        float kx3 = kp[2*kb+6], ky3 = kp[2*kb+7];
        bool f0=false, f1=false, f2=false, f3=false;
        for (int j = lane; j < NEP; j += 32) {
            float2 e = se[j];
            float dx, dy;
            dx = kx0-e.x; dy = ky0-e.y; f0 |= (dx*dx+dy*dy < 16.0f);
            dx = kx1-e.x; dy = ky1-e.y; f1 |= (dx*dx+dy*dy < 16.0f);
            dx = kx2-e.x; dy = ky2-e.y; f2 |= (dx*dx+dy*dy < 16.0f);
            dx = kx3-e.x; dy = ky3-e.y; f3 |= (dx*dx+dy*dy < 16.0f);
        }
        int a0 = __any_sync(0xffffffffu, f0);
        int a1 = __any_sync(0xffffffffu, f1);
        int a2 = __any_sync(0xffffffffu, f2);
        int a3 = __any_sync(0xffffffffu, f3);
        if (lane == 0) {
            g_suppress[kb]   = a0;
            g_suppress[kb+1] = a1;
            g_suppress[kb+2] = a2;
            g_suppress[kb+3] = a3;
        }
    } else if (role < 128) {
        int b = role - 64;
        int ib = b * 64 + (t >> 4) * 4;
        int jc = (t & 15) * 256;
        float2 p0 = se[ib], p1 = se[ib+1], p2 = se[ib+2], p3 = se[ib+3];
        for (int j = jc; j < jc + 256; ++j) {
            float2 e = se[j];
            float dx, dy;
            dx = p0.x-e.x; dy = p0.y-e.y;
            if (j > ib   && dx*dx+dy*dy <= 9.0f) { int x = atomicAdd(&s_cnt,1); if (x < EB_CAP) g_edges[b*EB_CAP+x] = (ib    <<16)|j; }
            dx = p1.x-e.x; dy = p1.y-e.y;
            if (j > ib+1 && dx*dx+dy*dy <= 9.0f) { int x = atomicAdd(&s_cnt,1); if (x < EB_CAP) g_edges[b*EB_CAP+x] = ((ib+1)<<16)|j; }
            dx = p2.x-e.x; dy = p2.y-e.y;
            if (j > ib+2 && dx*dx+dy*dy <= 9.0f) { int x = atomicAdd(&s_cnt,1); if (x < EB_CAP) g_edges[b*EB_CAP+x] = ((ib+2)<<16)|j; }
            dx = p3.x-e.x; dy = p3.y-e.y;
            if (j > ib+3 && dx*dx+dy*dy <= 9.0f) { int x = atomicAdd(&s_cnt,1); if (x < EB_CAP) g_edges[b*EB_CAP+x] = ((ib+3)<<16)|j; }
        }
        __syncthreads();
        if (t == 0) g_bcnt[b] = s_cnt < EB_CAP ? s_cnt : EB_CAP;
    } else {
        float v = -1e30f;
        for (int k = t; k < NLINES; k += 256) v = fmaxf(v, line_sc[k]);
        red[t] = v;
        __syncthreads();
        for (int s = 128; s > 0; s >>= 1) {
            if (t < s) red[t] = fmaxf(red[t], red[t + s]);
            __syncthreads();
        }
        float denom = 1e-8f + red[0];
        for (int k = t; k < NLINES; k += 256) out[OFF_LS + k] = line_sc[k] / denom;
    }
}

// =====================================================================
// k_mid: single block, 1024 threads — CC, rank, segment means, outputs
// =====================================================================
__global__ void __launch_bounds__(1024) k_mid(const float* __restrict__ lines,
                                              float* __restrict__ out) {
    extern __shared__ int sm[];
    int* lab  = sm;               // 4096
    int* rnk  = lab  + 4096;      // 4096
    int* imap = rnk  + 4096;      // 4096
    int* ax   = imap + 4096;      // 4096
    int* ay   = ax   + 4096;      // 4096
    int* as   = ay   + 4096;      // 4096
    int* cn   = as   + 4096;      // 4096
    int* sE   = cn   + 4096;      // SE_CAP
    int* scn  = sE   + SE_CAP;    // 1024
    int* soff = scn  + 1024;      // 65
    int* flg  = soff + 66;        // 1

    int t = threadIdx.x;

    if (t == 0) {
        int acc = 0;
        for (int b = 0; b < 64; ++b) { soff[b] = acc; acc += g_bcnt[b]; }
        soff[64] = acc;
    }
    for (int i = t; i < NEP; i += 1024) lab[i] = i;
    __syncthreads();
    int E = soff[64]; if (E > SE_CAP) E = SE_CAP;
    for (int s = t; s < 64 * EB_CAP; s += 1024) {
        int b = s / EB_CAP, e = s % EB_CAP;
        if (e < g_bcnt[b]) { int d = soff[b] + e; if (d < SE_CAP) sE[d] = g_edges[s]; }
    }
    __syncthreads();

    for (int it = 0; it < 64; ++it) {
        if (t == 0) flg[0] = 0;
        __syncthreads();
        for (int e = t; e < E; e += 1024) {
            int pr = sE[e];
            int i = pr >> 16, j = pr & 0xffff;
            int a = lab[i], b = lab[j];
            if (a < b)      { int old = atomicMin(&lab[j], a); if (old > a) flg[0] = 1; }
            else if (b < a) { int old = atomicMin(&lab[i], b); if (old > b) flg[0] = 1; }
        }
        __syncthreads();
        for (int i = t; i < NEP; i += 1024) {
            int l = lab[i], l2 = lab[l];
            if (l2 < l) { lab[i] = l2; flg[0] = 1; }
        }
        __syncthreads();
        int ch = flg[0];
        __syncthreads();
        if (!ch) break;
    }

    int base = t * 4;
    int pr4[4], pre[4], lsum = 0;
    #pragma unroll
    for (int k = 0; k < 4; ++k) {
        pr4[k] = (lab[base + k] == base + k) ? 1 : 0;
        pre[k] = lsum;
        lsum += pr4[k];
    }
    scn[t] = lsum;
    __syncthreads();
    for (int off = 1; off < 1024; off <<= 1) {
        int add = 0;
        if (t >= off) add = scn[t - off];
        __syncthreads();
        scn[t] += add;
        __syncthreads();
    }
    int excl = scn[t] - lsum;
    #pragma unroll
    for (int k = 0; k < 4; ++k) rnk[base + k] = excl + pre[k];
    __syncthreads();

    for (int s = t; s < NEP; s += 1024) {
        ax[s] = 0; ay[s] = 0; as[s] = 0; cn[s] = 0; imap[s] = -1;
    }
    __syncthreads();
    for (int i = t; i < NEP; i += 1024)
        if (lab[i] == i) imap[rnk[i]] = i;
    __syncthreads();

    const float2* ep2 = (const float2*)lines;
    for (int i = t; i < NEP; i += 1024) {
        float2 e = ep2[i];
        float sc = out[OFF_LS + (i >> 1)];
        int r = lab[i];
        atomicAdd(&ax[r], __float2int_rn(e.x * FX_COORD));
        atomicAdd(&ay[r], __float2int_rn(e.y * FX_COORD));
        atomicAdd(&as[r], __float2int_rn(sc * FX_SCORE));
        atomicAdd(&cn[r], 1);
    }
    __syncthreads();

    for (int s = t; s < NEP; s += 1024) {
        int r = imap[s];
        float jx = 0.f, jy = 0.f, js = 0.f;
        if (r >= 0) {
            float ic = 1.0f / (float)cn[r];
            jx = (float)ax[r] * (1.0f / FX_COORD) * ic;
            jy = (float)ay[r] * (1.0f / FX_COORD) * ic;
            js = (float)as[r] * (1.0f / FX_SCORE) * ic;
        }
        out[OFF_POINTS + 2*s]     = jx;
        out[OFF_POINTS + 2*s + 1] = jy;
        out[OFF_SCORES + s]       = js;
    }

    for (int e = t; e < NEP; e += 1024) {
        int r = lab[e];
        int c = rnk[r];
        float ic = 1.0f / (float)cn[r];
        out[OFF_NEWLINES + 2*e]     = (float)ax[r] * (1.0f / FX_COORD) * ic;
        out[OFF_NEWLINES + 2*e + 1] = (float)ay[r] * (1.0f / FX_COORD) * ic;
        out[OFF_JIDX + e]           = (float)c;
    }
}

// =====================================================================
// k_passA: role-switched
//   blocks [0,256)   : channel-plane staged bilinear sampling (unnormalized)
//   blocks [256,768) : float4 keypoint-descriptor copy (masked)
//   block  768       : keypoint points/scores
// =====================================================================
__global__ void __launch_bounds__(256) k_passA(const float* __restrict__ allD,
                                               const float* __restrict__ desc,
                                               const float* __restrict__ kp,
                                               const float* __restrict__ ksc,
                                               float* __restrict__ out) {
    extern __shared__ float spl[];       // 16384 floats = one channel plane
    int t = threadIdx.x;
    int role = blockIdx.x;

    if (role < 256) {
        // stage plane
        const float4* src = (const float4*)(allD + (size_t)role * (HC * WC));
        float4* dst = (float4*)spl;
        #pragma unroll
        for (int i = 0; i < 16; ++i) dst[i * 256 + t] = src[i * 256 + t];
        __syncthreads();

        float* orow = out + OFF_DESCS + (size_t)role * NTOT;
        const float2* pts = (const float2*)(out + OFF_POINTS);
        #pragma unroll
        for (int it = 0; it < 16; ++it) {
            int p = it * 256 + t;
            float2 pt = pts[p];
            float fx = (((pt.x - 3.5f) / 1019.5f) * 2.0f - 1.0f + 1.0f) * 0.5f * 127.0f;
            float fy = (((pt.y - 3.5f) / 1019.5f) * 2.0f - 1.0f + 1.0f) * 0.5f * 127.0f;
            float x0 = fminf(fmaxf(floorf(fx), 0.f), 127.f);
            float y0 = fminf(fmaxf(floorf(fy), 0.f), 127.f);
            float x1 = fminf(fmaxf(x0 + 1.0f, 0.f), 127.f);
            float y1 = fminf(fmaxf(y0 + 1.0f, 0.f), 127.f);
            float wx = fx - x0;
            float wy = fy - y0;
            int a00 = (int)y0 * WC + (int)x0;
            int a01 = (int)y0 * WC + (int)x1;
            int a10 = (int)y1 * WC + (int)x0;
            int a11 = (int)y1 * WC + (int)x1;
            float v = spl[a00] * (1.f - wx) * (1.f - wy)
                    + spl[a01] * wx * (1.f - wy)
                    + spl[a10] * (1.f - wx) * wy
                    + spl[a11] * wx * wy;
            orow[p] = v;     // unnormalized; pass B scales
        }
    } else if (role < 768) {
        int idx = (role - 256) * 256 + t;        // 131072 float4s
        int c  = idx >> 9;
        int kq = idx & 511;
        const float4* d4 = (const float4*)desc;
        float4 v = d4[c * 512 + kq];
        int k4 = kq * 4;
        if (g_suppress[k4])     v.x = 0.f;
        if (g_suppress[k4 + 1]) v.y = 0.f;
        if (g_suppress[k4 + 2]) v.z = 0.f;
        if (g_suppress[k4 + 3]) v.w = 0.f;
        float4* o4 = (float4*)(out + OFF_DESCS + c * NTOT + NEP);
        o4[kq] = v;
    } else {
        for (int k = t; k < NK; k += 256) {
            int sup = g_suppress[k];
            out[OFF_POINTS + 2*(NEP + k)]     = sup ? 0.f : kp[2*k];
            out[OFF_POINTS + 2*(NEP + k) + 1] = sup ? 0.f : kp[2*k + 1];
            out[OFF_SCORES + NEP + k]         = sup ? 0.f : ksc[k];
        }
    }
}

// =====================================================================
// k_passB: normalize junction descriptor columns.
//   128 blocks x 256 thr; block = 32 consecutive points; warp w handles
//   channels [32w,32w+32); all loads/stores coalesced (lane = point).
// =====================================================================
__global__ void __launch_bounds__(256) k_passB(float* __restrict__ out) {
    int w = threadIdx.x >> 5, lane = threadIdx.x & 31;
    int p = blockIdx.x * 32 + lane;

    float* ob = out + OFF_DESCS + (size_t)w * 32 * NTOT + p;
    float v[32];
    float ssq = 0.f;
    #pragma unroll
    for (int ci = 0; ci < 32; ++ci) {
        float vv = ob[ci * NTOT];
        v[ci] = vv;
        ssq += vv * vv;
    }

    __shared__ float sred[8][32];
    sred[w][lane] = ssq;
    __syncthreads();
    float tot = sred[0][lane] + sred[1][lane] + sred[2][lane] + sred[3][lane]
              + sred[4][lane] + sred[5][lane] + sred[6][lane] + sred[7][lane];
    float inv = 1.0f / fmaxf(sqrtf(tot), 1e-12f);

    #pragma unroll
    for (int ci = 0; ci < 32; ++ci)
        ob[ci * NTOT] = v[ci] * inv;
}

// ---------------- launch ----------------
extern "C" void kernel_launch(void* const* d_in, const int* in_sizes, int n_in,
                              void* d_out, int out_size) {
    const float* lines     = (const float*)d_in[0];
    const float* line_sc   = (const float*)d_in[1];
    const float* keypoints = (const float*)d_in[2];
    const float* kp_sc     = (const float*)d_in[3];
    const float* desc      = (const float*)d_in[4];
    const float* allD      = (const float*)d_in[5];
    float* out = (float*)d_out;

    static const int MID_SMEM = (4096 * 7 + SE_CAP + 1024 + 80) * 4;
    static const int PLANE_SMEM = HC * WC * 4;   // 64 KB
    cudaFuncSetAttribute(k_mid, cudaFuncAttributeMaxDynamicSharedMemorySize, MID_SMEM);
    cudaFuncSetAttribute(k_passA, cudaFuncAttributeMaxDynamicSharedMemorySize, PLANE_SMEM);

    k_front<<<129, 256>>>(lines, line_sc, keypoints, out);
    k_mid<<<1, 1024, MID_SMEM>>>(lines, out);
    k_passA<<<769, 256, PLANE_SMEM>>>(allD, desc, keypoints, kp_sc, out);
    k_passB<<<128, 256>>>(out);
}

// round 6
// speedup vs baseline: 2.3189x; 1.4075x over previous
#include <cuda_runtime.h>

// ---------------- problem constants ----------------
#define NLINES 2048
#define NEP    4096
#define NK     2048
#define NC     256
#define NTOT   6144
#define HC     128
#define WC     128
#define SE_CAP 4096          // smem edge cap (expected ~230)

// output offsets (float32, concatenated in reference return order)
#define OFF_POINTS   0
#define OFF_SCORES   12288
#define OFF_DESCS    18432
#define OFF_NEWLINES 1591296
#define OFF_JIDX     1599488
#define OFF_LS       1603584

// fixed-point scales (commutative integer sums -> deterministic)
#define FX_COORD 65536.0f
#define FX_SCORE 33554432.0f

__device__ int g_suppress[NK];
__device__ int g_done;

// =====================================================================
// k_geom: ONE block, 1024 threads. Uniform 64x64 cell grid (cell=16)
// replaces both O(N^2) passes. Then CC, rank, segment means, all small
// outputs. ~135KB dynamic smem.
// =====================================================================
__global__ void __launch_bounds__(1024) k_geom(const float* __restrict__ lines,
                                               const float* __restrict__ line_sc,
                                               const float* __restrict__ kp,
                                               const float* __restrict__ ksc,
                                               float* __restrict__ out) {
    extern __shared__ int dsm[];
    int* sxA  = dsm;            // phase1: sorted x      | phase2: rnk
    int* syA  = dsm + 4096;     //         sorted y      |         imap
    int* sidx = dsm + 8192;     //         orig idx      |         ax
    int* cst  = dsm + 12288;    //         cell start    |         ay
    int* ccn  = dsm + 16384;    //         cell count    |         as
    int* cid  = dsm + 20480;    //         per-pt cell   |         cn
    int* lab  = dsm + 24576;    // CC labels (orig idx)
    int* sE   = dsm + 28672;    // edge list
    int* scn  = dsm + 32768;    // 1024 scan tmp
    int* misc = dsm + 33792;    // [0]=edge cnt, [1]=change flag
    float* sred = (float*)scn;

    int t = threadIdx.x;
    const float2* ep2 = (const float2*)lines;

    if (t == 0) g_done = 0;     // reset spin counter for k_main (each replay)

    // ---- line-score normalization ----
    float mx = -1e30f;
    for (int k = t; k < NLINES; k += 1024) mx = fmaxf(mx, line_sc[k]);
    sred[t] = mx;
    __syncthreads();
    for (int s = 512; s > 0; s >>= 1) {
        if (t < s) sred[t] = fmaxf(sred[t], sred[t + s]);
        __syncthreads();
    }
    float denom = 1e-8f + sred[0];
    for (int k = t; k < NLINES; k += 1024) out[OFF_LS + k] = line_sc[k] / denom;
    __syncthreads();

    // ---- cell counts ----
    for (int i = t; i < 4096; i += 1024) { ccn[i] = 0; lab[i] = i; }
    __syncthreads();
    for (int i = t; i < 4096; i += 1024) {
        float2 e = ep2[i];
        int cx = min(63, max(0, (int)(e.x * 0.0625f)));
        int cy = min(63, max(0, (int)(e.y * 0.0625f)));
        int c = (cy << 6) | cx;
        cid[i] = c;
        atomicAdd(&ccn[c], 1);
    }
    __syncthreads();

    // ---- exclusive scan ccn -> cst ----
    {
        int base = t * 4;
        int v[4], pre[4], ls_ = 0;
        #pragma unroll
        for (int k = 0; k < 4; ++k) { v[k] = ccn[base + k]; pre[k] = ls_; ls_ += v[k]; }
        scn[t] = ls_;
        __syncthreads();
        for (int off = 1; off < 1024; off <<= 1) {
            int add = 0;
            if (t >= off) add = scn[t - off];
            __syncthreads();
            scn[t] += add;
            __syncthreads();
        }
        int excl = scn[t] - ls_;
        #pragma unroll
        for (int k = 0; k < 4; ++k) cst[base + k] = excl + pre[k];
    }
    __syncthreads();
    for (int i = t; i < 4096; i += 1024) ccn[i] = 0;
    __syncthreads();
    // scatter (order within cell nondet; downstream ops order-invariant)
    for (int i = t; i < 4096; i += 1024) {
        float2 e = ep2[i];
        int c = cid[i];
        int pos = cst[c] + atomicAdd(&ccn[c], 1);
        sxA[pos] = __float_as_int(e.x);
        syA[pos] = __float_as_int(e.y);
        sidx[pos] = i;
    }
    __syncthreads();

    // ---- keypoint suppression + kp point/score outputs ----
    for (int k = t; k < NK; k += 1024) {
        float kx = kp[2*k], ky = kp[2*k + 1];
        int x0 = max(0,  (int)floorf((kx - 4.f) * 0.0625f));
        int x1 = min(63, (int)floorf((kx + 4.f) * 0.0625f));
        int y0 = max(0,  (int)floorf((ky - 4.f) * 0.0625f));
        int y1 = min(63, (int)floorf((ky + 4.f) * 0.0625f));
        bool sup = false;
        for (int cy = y0; cy <= y1; ++cy)
            for (int cx = x0; cx <= x1; ++cx) {
                int c = (cy << 6) | cx;
                int st = cst[c], en = st + ccn[c];
                for (int j = st; j < en; ++j) {
                    float dx = kx - __int_as_float(sxA[j]);
                    float dy = ky - __int_as_float(syA[j]);
                    if (dx*dx + dy*dy < 16.f) sup = true;
                }
            }
        g_suppress[k] = sup ? 1 : 0;
        out[OFF_POINTS + 2*(NEP + k)]     = sup ? 0.f : kx;
        out[OFF_POINTS + 2*(NEP + k) + 1] = sup ? 0.f : ky;
        out[OFF_SCORES + NEP + k]         = sup ? 0.f : ksc[k];
    }

    // ---- edge build via grid ----
    if (t == 0) misc[0] = 0;
    __syncthreads();
    for (int i = t; i < 4096; i += 1024) {
        float2 e = ep2[i];
        int x0 = max(0,  (int)floorf((e.x - 3.f) * 0.0625f));
        int x1 = min(63, (int)floorf((e.x + 3.f) * 0.0625f));
        int y0 = max(0,  (int)floorf((e.y - 3.f) * 0.0625f));
        int y1 = min(63, (int)floorf((e.y + 3.f) * 0.0625f));
        for (int cy = y0; cy <= y1; ++cy)
            for (int cx = x0; cx <= x1; ++cx) {
                int c = (cy << 6) | cx;
                int st = cst[c], en = st + ccn[c];
                for (int j = st; j < en; ++j) {
                    int oj = sidx[j];
                    if (oj <= i) continue;
                    float dx = e.x - __int_as_float(sxA[j]);
                    float dy = e.y - __int_as_float(syA[j]);
                    if (dx*dx + dy*dy <= 9.f) {
                        int x = atomicAdd(&misc[0], 1);
                        if (x < SE_CAP) sE[x] = (i << 16) | oj;
                    }
                }
            }
    }
    __syncthreads();
    int E = misc[0]; if (E > SE_CAP) E = SE_CAP;

    // ---- connected components (min-label fixpoint; schedule-invariant) ----
    for (int it = 0; it < 64; ++it) {
        if (t == 0) misc[1] = 0;
        __syncthreads();
        for (int e = t; e < E; e += 1024) {
            int pr = sE[e];
            int i = pr >> 16, j = pr & 0xffff;
            int a = lab[i], b = lab[j];
            if (a < b)      { int old = atomicMin(&lab[j], a); if (old > a) misc[1] = 1; }
            else if (b < a) { int old = atomicMin(&lab[i], b); if (old > b) misc[1] = 1; }
        }
        __syncthreads();
        for (int i = t; i < 4096; i += 1024) {
            int l = lab[i], l2 = lab[l];
            if (l2 < l) { lab[i] = l2; misc[1] = 1; }
        }
        __syncthreads();
        int ch = misc[1];
        __syncthreads();
        if (!ch) break;
    }

    // ---- dense rank of roots (phase1 arrays now dead -> reuse) ----
    int* rnk  = sxA;
    int* imap = syA;
    int* ax   = sidx;
    int* ay   = cst;
    int* as_  = ccn;
    int* cn   = cid;
    {
        int base = t * 4;
        int p4[4], pre[4], lsum = 0;
        #pragma unroll
        for (int k = 0; k < 4; ++k) {
            p4[k] = (lab[base + k] == base + k) ? 1 : 0;
            pre[k] = lsum;
            lsum += p4[k];
        }
        scn[t] = lsum;
        __syncthreads();
        for (int off = 1; off < 1024; off <<= 1) {
            int add = 0;
            if (t >= off) add = scn[t - off];
            __syncthreads();
            scn[t] += add;
            __syncthreads();
        }
        int excl = scn[t] - lsum;
        #pragma unroll
        for (int k = 0; k < 4; ++k) rnk[base + k] = excl + pre[k];
    }
    __syncthreads();

    for (int s = t; s < 4096; s += 1024) {
        ax[s] = 0; ay[s] = 0; as_[s] = 0; cn[s] = 0; imap[s] = -1;
    }
    __syncthreads();
    for (int i = t; i < 4096; i += 1024)
        if (lab[i] == i) imap[rnk[i]] = i;
    __syncthreads();

    // ---- fixed-point segment sums ----
    for (int i = t; i < 4096; i += 1024) {
        float2 e = ep2[i];
        float sc = out[OFF_LS + (i >> 1)];
        int r = lab[i];
        atomicAdd(&ax[r],  __float2int_rn(e.x * FX_COORD));
        atomicAdd(&ay[r],  __float2int_rn(e.y * FX_COORD));
        atomicAdd(&as_[r], __float2int_rn(sc * FX_SCORE));
        atomicAdd(&cn[r], 1);
    }
    __syncthreads();

    // ---- junction points/scores ----
    for (int s = t; s < 4096; s += 1024) {
        int r = imap[s];
        float jx = 0.f, jy = 0.f, js = 0.f;
        if (r >= 0) {
            float ic = 1.0f / (float)cn[r];
            jx = (float)ax[r]  * (1.0f / FX_COORD) * ic;
            jy = (float)ay[r]  * (1.0f / FX_COORD) * ic;
            js = (float)as_[r] * (1.0f / FX_SCORE) * ic;
        }
        out[OFF_POINTS + 2*s]     = jx;
        out[OFF_POINTS + 2*s + 1] = jy;
        out[OFF_SCORES + s]       = js;
    }

    // ---- new_lines + lines_junc_idx ----
    for (int e = t; e < 4096; e += 1024) {
        int r = lab[e];
        float ic = 1.0f / (float)cn[r];
        out[OFF_NEWLINES + 2*e]     = (float)ax[r] * (1.0f / FX_COORD) * ic;
        out[OFF_NEWLINES + 2*e + 1] = (float)ay[r] * (1.0f / FX_COORD) * ic;
        out[OFF_JIDX + e]           = (float)rnk[r];
    }
}

// =====================================================================
// k_main: 896 blocks x 256 thr, 64KB dyn smem
//   [0,256)   : channel-plane staged sampling (unnormalized) -> g_done++
//   [256,768) : float4 keypoint-descriptor copy (masked)
//   [768,896) : normalize (spins until g_done==256)
// Deadlock-safe: >=3 blocks/SM resident at 64KB => >=444 slots >> 128 spinners.
// =====================================================================
__global__ void __launch_bounds__(256) k_main(const float* __restrict__ allD,
                                              const float* __restrict__ desc,
                                              float* __restrict__ out) {
    extern __shared__ float spl[];
    int t = threadIdx.x;
    int role = blockIdx.x;

    if (role < 256) {
        const float4* src = (const float4*)(allD + (size_t)role * (HC * WC));
        float4* dst = (float4*)spl;
        #pragma unroll
        for (int i = 0; i < 16; ++i) dst[i * 256 + t] = src[i * 256 + t];
        __syncthreads();

        float* orow = out + OFF_DESCS + (size_t)role * NTOT;
        const float2* pts = (const float2*)(out + OFF_POINTS);
        #pragma unroll
        for (int it = 0; it < 16; ++it) {
            int p = it * 256 + t;
            float2 pt = pts[p];
            float fx = (((pt.x - 3.5f) / 1019.5f) * 2.0f) * 0.5f * 127.0f;
            float fy = (((pt.y - 3.5f) / 1019.5f) * 2.0f) * 0.5f * 127.0f;
            float x0 = fminf(fmaxf(floorf(fx), 0.f), 127.f);
            float y0 = fminf(fmaxf(floorf(fy), 0.f), 127.f);
            float x1 = fminf(fmaxf(x0 + 1.0f, 0.f), 127.f);
            float y1 = fminf(fmaxf(y0 + 1.0f, 0.f), 127.f);
            float wx = fx - x0;
            float wy = fy - y0;
            int a00 = (int)y0 * WC + (int)x0;
            int a01 = (int)y0 * WC + (int)x1;
            int a10 = (int)y1 * WC + (int)x0;
            int a11 = (int)y1 * WC + (int)x1;
            float v = spl[a00] * (1.f - wx) * (1.f - wy)
                    + spl[a01] * wx * (1.f - wy)
                    + spl[a10] * (1.f - wx) * wy
                    + spl[a11] * wx * wy;
            orow[p] = v;
        }
        // publish (threadFenceReduction pattern)
        __threadfence();
        __syncthreads();
        if (t == 0) atomicAdd(&g_done, 1);
    } else if (role < 768) {
        int idx = (role - 256) * 256 + t;
        int c  = idx >> 9;
        int kq = idx & 511;
        const float4* d4 = (const float4*)desc;
        float4 v = d4[c * 512 + kq];
        int k4 = kq * 4;
        if (g_suppress[k4])     v.x = 0.f;
        if (g_suppress[k4 + 1]) v.y = 0.f;
        if (g_suppress[k4 + 2]) v.z = 0.f;
        if (g_suppress[k4 + 3]) v.w = 0.f;
        float4* o4 = (float4*)(out + OFF_DESCS + c * NTOT + NEP);
        o4[kq] = v;
    } else {
        if (t == 0) {
            while (atomicAdd(&g_done, 0) < 256) __nanosleep(256);
        }
        __syncthreads();
        __threadfence();

        int w = t >> 5, lane = t & 31;
        int p = (role - 768) * 32 + lane;
        float* ob = out + OFF_DESCS + (size_t)w * 32 * NTOT + p;
        float v[32];
        float ssq = 0.f;
        #pragma unroll
        for (int ci = 0; ci < 32; ++ci) {
            float vv = ob[ci * NTOT];
            v[ci] = vv;
            ssq += vv * vv;
        }
        __shared__ float sred[8][32];
        sred[w][lane] = ssq;
        __syncthreads();
        float tot = sred[0][lane] + sred[1][lane] + sred[2][lane] + sred[3][lane]
                  + sred[4][lane] + sred[5][lane] + sred[6][lane] + sred[7][lane];
        float inv = 1.0f / fmaxf(sqrtf(tot), 1e-12f);
        #pragma unroll
        for (int ci = 0; ci < 32; ++ci)
            ob[ci * NTOT] = v[ci] * inv;
    }
}

// Note: fx computes ((g+1)*0.5*127) with g = ((px-3.5)/1019.5)*2-1, i.e.
// fx = (((px-3.5)/1019.5)*2 - 1 + 1)*0.5*127 = ((px-3.5)/1019.5)*127.
// The expression above folds the -1+1.

// ---------------- launch ----------------
extern "C" void kernel_launch(void* const* d_in, const int* in_sizes, int n_in,
                              void* d_out, int out_size) {
    const float* lines     = (const float*)d_in[0];
    const float* line_sc   = (const float*)d_in[1];
    const float* keypoints = (const float*)d_in[2];
    const float* kp_sc     = (const float*)d_in[3];
    const float* desc      = (const float*)d_in[4];
    const float* allD      = (const float*)d_in[5];
    float* out = (float*)d_out;

    static const int GEOM_SMEM  = (33792 + 8) * 4;      // ~135.2 KB
    static const int PLANE_SMEM = HC * WC * 4;          // 64 KB
    cudaFuncSetAttribute(k_geom, cudaFuncAttributeMaxDynamicSharedMemorySize, GEOM_SMEM);
    cudaFuncSetAttribute(k_main, cudaFuncAttributeMaxDynamicSharedMemorySize, PLANE_SMEM);

    k_geom<<<1, 1024, GEOM_SMEM>>>(lines, line_sc, keypoints, kp_sc, out);
    k_main<<<896, 256, PLANE_SMEM>>>(allD, desc, out);
}